// round 1
// baseline (speedup 1.0000x reference)
#include <cuda_runtime.h>
#include <cuda_bf16.h>

// LSTMSimulator: B=8192 independent sequences, T=2048, N_IN=1, N_H=32, N_OUT=1.
// Strategy: one warp per batch element, persistent over all T steps.
// Lane l owns gate rows {l, l+32, l+64, l+96} of W_hh in registers (128 regs),
// h is distributed one element per lane and broadcast via shfl per step.

#define NH 32
#define T_LEN 2048

__device__ __forceinline__ float fsig(float v) {
    // 1 / (1 + e^-v); MUFU.EX2 + MUFU.RCP path, ~1e-6 rel err
    return __fdividef(1.0f, 1.0f + __expf(-v));
}

__device__ __forceinline__ float ftanhf(float v) {
    // tanh via exp, sign-safe: t = e^{-2|v|}; tanh = sign(v) * (1-t)/(1+t)
    float t = __expf(-2.0f * fabsf(v));
    float r = __fdividef(1.0f - t, 1.0f + t);
    return copysignf(r, v);
}

__global__ void __launch_bounds__(128, 3)
lstm_warp_kernel(const float* __restrict__ input,   // [B, T, 1]
                 const float* __restrict__ W_ih,    // [4*NH, 1]
                 const float* __restrict__ W_hh,    // [4*NH, NH]
                 const float* __restrict__ b_ih,    // [4*NH]
                 const float* __restrict__ b_hh,    // [4*NH]
                 const float* __restrict__ W_lin,   // [1, NH]
                 const float* __restrict__ b_lin,   // [1]
                 float* __restrict__ out,           // [B, T, 1]
                 int B, int T)
{
    const int gwarp = (blockIdx.x * blockDim.x + threadIdx.x) >> 5;
    const int lane  = threadIdx.x & 31;
    if (gwarp >= B) return;

    const float* xin  = input + (size_t)gwarp * T;
    float*       yout = out   + (size_t)gwarp * T;

    // ---- load per-lane weights into registers ----
    // gate order (PyTorch LSTMCell): i rows [0,32), f [32,64), g [64,96), o [96,128)
    float wI[NH], wF[NH], wG[NH], wO[NH];
    {
        const float4* pI = (const float4*)(W_hh + (size_t)(lane      ) * NH);
        const float4* pF = (const float4*)(W_hh + (size_t)(lane + 32 ) * NH);
        const float4* pG = (const float4*)(W_hh + (size_t)(lane + 64 ) * NH);
        const float4* pO = (const float4*)(W_hh + (size_t)(lane + 96 ) * NH);
        #pragma unroll
        for (int q = 0; q < NH / 4; q++) {
            float4 a = pI[q]; wI[4*q]=a.x; wI[4*q+1]=a.y; wI[4*q+2]=a.z; wI[4*q+3]=a.w;
            float4 b = pF[q]; wF[4*q]=b.x; wF[4*q+1]=b.y; wF[4*q+2]=b.z; wF[4*q+3]=b.w;
            float4 c = pG[q]; wG[4*q]=c.x; wG[4*q+1]=c.y; wG[4*q+2]=c.z; wG[4*q+3]=c.w;
            float4 d = pO[q]; wO[4*q]=d.x; wO[4*q+1]=d.y; wO[4*q+2]=d.z; wO[4*q+3]=d.w;
        }
    }
    const float uI = W_ih[lane];
    const float uF = W_ih[lane + 32];
    const float uG = W_ih[lane + 64];
    const float uO = W_ih[lane + 96];
    const float bI = b_ih[lane]      + b_hh[lane];
    const float bF = b_ih[lane + 32] + b_hh[lane + 32];
    const float bG = b_ih[lane + 64] + b_hh[lane + 64];
    const float bO = b_ih[lane + 96] + b_hh[lane + 96];
    const float wlin = W_lin[lane];
    const float blin = b_lin[0];

    float h = 0.0f, c = 0.0f;

    #pragma unroll 1
    for (int t = 0; t < T; t++) {
        const float x = __ldg(xin + t);   // all lanes same address: 1 sector, L1-resident

        float aI = fmaf(x, uI, bI);
        float aF = fmaf(x, uF, bF);
        float aG = fmaf(x, uG, bG);
        float aO = fmaf(x, uO, bO);

        #pragma unroll
        for (int k = 0; k < NH; k++) {
            const float hk = __shfl_sync(0xffffffffu, h, k);
            aI = fmaf(hk, wI[k], aI);
            aF = fmaf(hk, wF[k], aF);
            aG = fmaf(hk, wG[k], aG);
            aO = fmaf(hk, wO[k], aO);
        }

        const float ig = fsig(aI);
        const float fg = fsig(aF);
        const float gg = ftanhf(aG);
        const float og = fsig(aO);

        c = fmaf(fg, c, ig * gg);
        h = og * ftanhf(c);

        // y_t = sum_l h[l] * W_lin[l] + b_lin  (butterfly reduce; off next-step critical path)
        float y = h * wlin;
        #pragma unroll
        for (int off = 16; off > 0; off >>= 1)
            y += __shfl_xor_sync(0xffffffffu, y, off);
        if (lane == 0) yout[t] = y + blin;
    }
}

extern "C" void kernel_launch(void* const* d_in, const int* in_sizes, int n_in,
                              void* d_out, int out_size)
{
    const float* input = (const float*)d_in[0];
    const float* W_ih  = (const float*)d_in[1];
    const float* W_hh  = (const float*)d_in[2];
    const float* b_ih  = (const float*)d_in[3];
    const float* b_hh  = (const float*)d_in[4];
    const float* W_lin = (const float*)d_in[5];
    const float* b_lin = (const float*)d_in[6];
    float* out = (float*)d_out;

    const int T = T_LEN;
    const int B = in_sizes[0] / T;           // N_IN == 1

    const int threads = 128;                 // 4 warps -> 4 batch rows per block
    const int blocks  = (B * 32 + threads - 1) / threads;
    lstm_warp_kernel<<<blocks, threads>>>(input, W_ih, W_hh, b_ih, b_hh,
                                          W_lin, b_lin, out, B, T);
}